// round 6
// baseline (speedup 1.0000x reference)
#include <cuda_runtime.h>
#include <math.h>

// Problem constants
#define T_TOK   4096          // BATCH * SEQ
#define DM      1024          // d_model
#define HID     2048          // hidden
#define NE      8             // experts
#define NSLOTS  (T_TOK * 2)   // T * TOP_K

// ---------------- device scratch (no allocations allowed) ----------------
__device__ __align__(16) float g_act[(size_t)NSLOTS * HID];  // 64 MB activation scratch
__device__ int   g_cnt[NE];
__device__ int   g_off[NE + 1];
__device__ int   g_cursor[NE];
__device__ int   g_top_e[NSLOTS];
__device__ float g_top_g[NSLOTS];
__device__ int   g_perm_tok[NSLOTS];
__device__ float g_perm_gate[NSLOTS];

// ---------------- small kernels ----------------
__global__ void zero_counts_kernel() {
    int i = threadIdx.x;
    if (i < NE) g_cnt[i] = 0;
}

// One block (256 thr = 8 warps) per token: warp w computes logit for expert w.
__global__ void router_kernel(const float* __restrict__ x,
                              const float* __restrict__ wr) {
    int t = blockIdx.x;
    int tid = threadIdx.x;
    int w = tid >> 5, lane = tid & 31;
    const float* xr = x + (size_t)t * DM;
    float partial = 0.f;
    for (int d = lane; d < DM; d += 32)
        partial += xr[d] * wr[d * NE + w];
    #pragma unroll
    for (int o = 16; o; o >>= 1)
        partial += __shfl_xor_sync(0xffffffffu, partial, o);
    __shared__ float logits[NE];
    if (lane == 0) logits[w] = partial;
    __syncthreads();
    if (tid == 0) {
        float mx = logits[0];
        #pragma unroll
        for (int e = 1; e < NE; e++) mx = fmaxf(mx, logits[e]);
        float p[NE];
        #pragma unroll
        for (int e = 0; e < NE; e++) p[e] = expf(logits[e] - mx);
        // top-2, lowest index wins ties (matches jax.lax.top_k)
        int e0 = 0;
        #pragma unroll
        for (int e = 1; e < NE; e++) if (p[e] > p[e0]) e0 = e;
        int e1 = (e0 == 0) ? 1 : 0;
        #pragma unroll
        for (int e = 0; e < NE; e++) if (e != e0 && p[e] > p[e1]) e1 = e;
        float s2 = p[e0] + p[e1];              // renormalized gates
        g_top_e[2 * t]     = e0; g_top_g[2 * t]     = p[e0] / s2;
        g_top_e[2 * t + 1] = e1; g_top_g[2 * t + 1] = p[e1] / s2;
        atomicAdd(&g_cnt[e0], 1);
        atomicAdd(&g_cnt[e1], 1);
    }
}

__global__ void scan_kernel() {
    if (threadIdx.x == 0) {
        int acc = 0;
        for (int e = 0; e < NE; e++) {
            g_off[e] = acc;
            acc += g_cnt[e];
            g_cursor[e] = 0;
        }
        g_off[NE] = acc;
    }
}

__global__ void scatter_kernel() {
    int t = blockIdx.x * blockDim.x + threadIdx.x;
    if (t >= T_TOK) return;
    #pragma unroll
    for (int k = 0; k < 2; k++) {
        int e = g_top_e[2 * t + k];
        int pos = g_off[e] + atomicAdd(&g_cursor[e], 1);
        g_perm_tok[pos]  = t;
        g_perm_gate[pos] = g_top_g[2 * t + k];
    }
}

// ---------------- GEMM1: A = silu(Xg*W1) * (Xg*W3), 128x64 tile, dual accum ----
// ROUTED: rows segmented per expert via g_off, rows gathered via g_perm_tok.
// !ROUTED: identity rows [0, Mtot), W1/W3 = shared-expert weights.
template <bool ROUTED>
__global__ void __launch_bounds__(256, 2)
gemm1_swiglu(const float* __restrict__ X,
             const float* __restrict__ W1,
             const float* __restrict__ W3,
             int Mtot) {
    int r0, r1;
    if (ROUTED) { int e = blockIdx.z; r0 = g_off[e]; r1 = g_off[e + 1]; }
    else        { r0 = 0; r1 = Mtot; }
    int mBase = r0 + blockIdx.x * 128;
    if (mBase >= r1) return;
    int n0 = blockIdx.y * 64;

    const float* w1 = W1;
    const float* w3 = W3;
    if (ROUTED) {
        size_t eoff = (size_t)blockIdx.z * DM * HID;
        w1 += eoff; w3 += eoff;
    }

    __shared__ __align__(16) float Xs[8][128];
    __shared__ __align__(16) float W1s[8][64];
    __shared__ __align__(16) float W3s[8][64];

    int tid = threadIdx.x;
    int tx = tid & 15, ty = tid >> 4;

    // X staging: thread loads float4 of row (tid>>1), k-half (tid&1)
    int mload = tid >> 1;
    int half  = tid & 1;
    int lslot = mBase + mload;
    bool lvalid = (lslot < r1);
    const float* xrow = X;
    if (lvalid) {
        int tok = ROUTED ? g_perm_tok[lslot] : lslot;
        xrow = X + (size_t)tok * DM + half * 4;
    }

    // W staging: tid<128 -> W1, tid>=128 -> W3; 8 k-rows x 16 float4 cols
    int wk = (tid & 127) >> 4;
    int wn = tid & 15;
    bool isW3 = (tid >= 128);
    const float* wsrc = (isW3 ? w3 : w1) + (size_t)wk * HID + n0 + wn * 4;

    float acc1[8][4], acc3[8][4];
    #pragma unroll
    for (int i = 0; i < 8; i++)
        #pragma unroll
        for (int j = 0; j < 4; j++) { acc1[i][j] = 0.f; acc3[i][j] = 0.f; }

    for (int k0 = 0; k0 < DM; k0 += 8) {
        float4 xv = lvalid ? *(const float4*)(xrow + k0)
                           : make_float4(0.f, 0.f, 0.f, 0.f);
        Xs[half * 4 + 0][mload] = xv.x;
        Xs[half * 4 + 1][mload] = xv.y;
        Xs[half * 4 + 2][mload] = xv.z;
        Xs[half * 4 + 3][mload] = xv.w;

        float4 wv = *(const float4*)(wsrc + (size_t)k0 * HID);
        if (isW3) *(float4*)&W3s[wk][wn * 4] = wv;
        else      *(float4*)&W1s[wk][wn * 4] = wv;
        __syncthreads();

        #pragma unroll
        for (int kk = 0; kk < 8; kk++) {
            float4 a0 = *(const float4*)&Xs[kk][ty * 4];
            float4 a1 = *(const float4*)&Xs[kk][64 + ty * 4];
            float4 b1 = *(const float4*)&W1s[kk][tx * 4];
            float4 b3 = *(const float4*)&W3s[kk][tx * 4];
            float a[8]  = {a0.x, a0.y, a0.z, a0.w, a1.x, a1.y, a1.z, a1.w};
            float p1[4] = {b1.x, b1.y, b1.z, b1.w};
            float p3[4] = {b3.x, b3.y, b3.z, b3.w};
            #pragma unroll
            for (int i = 0; i < 8; i++)
                #pragma unroll
                for (int j = 0; j < 4; j++) {
                    acc1[i][j] = fmaf(a[i], p1[j], acc1[i][j]);
                    acc3[i][j] = fmaf(a[i], p3[j], acc3[i][j]);
                }
        }
        __syncthreads();
    }

    // SwiGLU epilogue -> g_act[slot, n]
    #pragma unroll
    for (int i = 0; i < 8; i++) {
        int m = (i < 4) ? (ty * 4 + i) : (64 + ty * 4 + i - 4);
        int slot = mBase + m;
        if (slot < r1) {
            float v[4];
            #pragma unroll
            for (int j = 0; j < 4; j++) {
                float h1 = acc1[i][j], h3 = acc3[i][j];
                v[j] = (h1 / (1.f + expf(-h1))) * h3;   // silu(h1)*h3
            }
            *(float4*)&g_act[(size_t)slot * HID + n0 + tx * 4] =
                make_float4(v[0], v[1], v[2], v[3]);
        }
    }
}

// ---------------- GEMM2: Y = A * W2, 128x128 tile, 8x8 micro-tile ----------
// ROUTED: gate-scaled atomicAdd scatter into out[token]. !ROUTED: plain store.
template <bool ROUTED>
__global__ void __launch_bounds__(256, 2)
gemm2_comb(const float* __restrict__ W2,
           float* __restrict__ out,
           int Mtot) {
    int r0, r1;
    if (ROUTED) { int e = blockIdx.z; r0 = g_off[e]; r1 = g_off[e + 1]; }
    else        { r0 = 0; r1 = Mtot; }
    int mBase = r0 + blockIdx.x * 128;
    if (mBase >= r1) return;
    int n0 = blockIdx.y * 128;

    const float* w2 = W2;
    if (ROUTED) w2 += (size_t)blockIdx.z * HID * DM;

    __shared__ __align__(16) float As[8][128];
    __shared__ __align__(16) float Ws[8][128];

    int tid = threadIdx.x;
    int tx = tid & 15, ty = tid >> 4;
    int mload = tid >> 1, half = tid & 1;
    int lslot = mBase + mload;
    bool lvalid = (lslot < r1);
    size_t arow_off = (size_t)(lvalid ? lslot : r0) * HID + half * 4;

    int wk = tid >> 5, wn = tid & 31;   // 8 k-rows x 32 float4 cols
    const float* wptr = w2 + (size_t)wk * DM + n0 + wn * 4;

    float acc[8][8];
    #pragma unroll
    for (int i = 0; i < 8; i++)
        #pragma unroll
        for (int j = 0; j < 8; j++) acc[i][j] = 0.f;

    for (int k0 = 0; k0 < HID; k0 += 8) {
        float4 av = lvalid ? *(const float4*)&g_act[arow_off + k0]
                           : make_float4(0.f, 0.f, 0.f, 0.f);
        As[half * 4 + 0][mload] = av.x;
        As[half * 4 + 1][mload] = av.y;
        As[half * 4 + 2][mload] = av.z;
        As[half * 4 + 3][mload] = av.w;

        float4 wv = *(const float4*)(wptr + (size_t)k0 * DM);
        *(float4*)&Ws[wk][wn * 4] = wv;
        __syncthreads();

        #pragma unroll
        for (int kk = 0; kk < 8; kk++) {
            float4 a0 = *(const float4*)&As[kk][ty * 4];
            float4 a1 = *(const float4*)&As[kk][64 + ty * 4];
            float4 b0 = *(const float4*)&Ws[kk][tx * 4];
            float4 b1 = *(const float4*)&Ws[kk][64 + tx * 4];
            float a[8] = {a0.x, a0.y, a0.z, a0.w, a1.x, a1.y, a1.z, a1.w};
            float b[8] = {b0.x, b0.y, b0.z, b0.w, b1.x, b1.y, b1.z, b1.w};
            #pragma unroll
            for (int i = 0; i < 8; i++)
                #pragma unroll
                for (int j = 0; j < 8; j++)
                    acc[i][j] = fmaf(a[i], b[j], acc[i][j]);
        }
        __syncthreads();
    }

    #pragma unroll
    for (int i = 0; i < 8; i++) {
        int m = (i < 4) ? (ty * 4 + i) : (64 + ty * 4 + i - 4);
        int slot = mBase + m;
        if (slot >= r1) continue;
        if (ROUTED) {
            int tok  = g_perm_tok[slot];
            float g  = g_perm_gate[slot];
            float* dst = out + (size_t)tok * DM + n0;
            #pragma unroll
            for (int j = 0; j < 8; j++) {
                int c = (j < 4) ? (tx * 4 + j) : (64 + tx * 4 + j - 4);
                atomicAdd(dst + c, g * acc[i][j]);
            }
        } else {
            float* dst = out + (size_t)slot * DM + n0;
            *(float4*)(dst + tx * 4) =
                make_float4(acc[i][0], acc[i][1], acc[i][2], acc[i][3]);
            *(float4*)(dst + 64 + tx * 4) =
                make_float4(acc[i][4], acc[i][5], acc[i][6], acc[i][7]);
        }
    }
}

// ---------------- launch ----------------
extern "C" void kernel_launch(void* const* d_in, const int* in_sizes, int n_in,
                              void* d_out, int out_size) {
    (void)in_sizes; (void)n_in; (void)out_size;
    const float* x   = (const float*)d_in[0];
    const float* wr  = (const float*)d_in[1];
    const float* w1  = (const float*)d_in[2];
    const float* w3  = (const float*)d_in[3];
    const float* w2  = (const float*)d_in[4];
    const float* sw1 = (const float*)d_in[5];
    const float* sw3 = (const float*)d_in[6];
    const float* sw2 = (const float*)d_in[7];
    float* out = (float*)d_out;

    // Routing
    zero_counts_kernel<<<1, 32>>>();
    router_kernel<<<T_TOK, 256>>>(x, wr);
    scan_kernel<<<1, 32>>>();
    scatter_kernel<<<(T_TOK + 255) / 256, 256>>>();

    // Shared expert first (writes every out element -> covers 0xAA poison)
    gemm1_swiglu<false><<<dim3(T_TOK / 128, HID / 64, 1), 256>>>(x, sw1, sw3, T_TOK);
    gemm2_comb<false><<<dim3(T_TOK / 128, DM / 128, 1), 256>>>(sw2, out, T_TOK);

    // Routed experts (reuse g_act scratch; stream order guarantees safety)
    gemm1_swiglu<true><<<dim3(NSLOTS / 128, HID / 64, NE), 256>>>(x, w1, w3, 0);
    gemm2_comb<true><<<dim3(NSLOTS / 128, DM / 128, NE), 256>>>(w2, out, 0);
}

// round 7
// speedup vs baseline: 1.0003x; 1.0003x over previous
#include <cuda_runtime.h>
#include <math.h>

// Problem constants
#define T_TOK   4096          // BATCH * SEQ
#define DM      1024          // d_model
#define HID     2048          // hidden
#define NE      8             // experts
#define NSLOTS  (T_TOK * 2)   // T * TOP_K

// ---------------- device scratch (no allocations allowed) ----------------
__device__ __align__(16) float g_act[(size_t)NSLOTS * HID];  // 64 MB activation scratch
__device__ int   g_cnt[NE];
__device__ int   g_off[NE + 1];
__device__ int   g_cursor[NE];
__device__ int   g_top_e[NSLOTS];
__device__ float g_top_g[NSLOTS];
__device__ int   g_perm_tok[NSLOTS];
__device__ float g_perm_gate[NSLOTS];

// ---------------- small kernels ----------------
__global__ void zero_counts_kernel() {
    int i = threadIdx.x;
    if (i < NE) g_cnt[i] = 0;
}

// One block (256 thr = 8 warps) per token: warp w computes logit for expert w.
__global__ void router_kernel(const float* __restrict__ x,
                              const float* __restrict__ wr) {
    int t = blockIdx.x;
    int tid = threadIdx.x;
    int w = tid >> 5, lane = tid & 31;
    const float* xr = x + (size_t)t * DM;
    float partial = 0.f;
    for (int d = lane; d < DM; d += 32)
        partial += xr[d] * wr[d * NE + w];
    #pragma unroll
    for (int o = 16; o; o >>= 1)
        partial += __shfl_xor_sync(0xffffffffu, partial, o);
    __shared__ float logits[NE];
    if (lane == 0) logits[w] = partial;
    __syncthreads();
    if (tid == 0) {
        float mx = logits[0];
        #pragma unroll
        for (int e = 1; e < NE; e++) mx = fmaxf(mx, logits[e]);
        float p[NE];
        #pragma unroll
        for (int e = 0; e < NE; e++) p[e] = expf(logits[e] - mx);
        // top-2, lowest index wins ties (matches jax.lax.top_k)
        int e0 = 0;
        #pragma unroll
        for (int e = 1; e < NE; e++) if (p[e] > p[e0]) e0 = e;
        int e1 = (e0 == 0) ? 1 : 0;
        #pragma unroll
        for (int e = 0; e < NE; e++) if (e != e0 && p[e] > p[e1]) e1 = e;
        float s2 = p[e0] + p[e1];              // renormalized gates
        g_top_e[2 * t]     = e0; g_top_g[2 * t]     = p[e0] / s2;
        g_top_e[2 * t + 1] = e1; g_top_g[2 * t + 1] = p[e1] / s2;
        atomicAdd(&g_cnt[e0], 1);
        atomicAdd(&g_cnt[e1], 1);
    }
}

__global__ void scan_kernel() {
    if (threadIdx.x == 0) {
        int acc = 0;
        for (int e = 0; e < NE; e++) {
            g_off[e] = acc;
            acc += g_cnt[e];
            g_cursor[e] = 0;
        }
        g_off[NE] = acc;
    }
}

__global__ void scatter_kernel() {
    int t = blockIdx.x * blockDim.x + threadIdx.x;
    if (t >= T_TOK) return;
    #pragma unroll
    for (int k = 0; k < 2; k++) {
        int e = g_top_e[2 * t + k];
        int pos = g_off[e] + atomicAdd(&g_cursor[e], 1);
        g_perm_tok[pos]  = t;
        g_perm_gate[pos] = g_top_g[2 * t + k];
    }
}

// ---------------- GEMM1: A = silu(Xg*W1) * (Xg*W3), 128x64 tile, dual accum ----
// ROUTED: rows segmented per expert via g_off, rows gathered via g_perm_tok.
// !ROUTED: identity rows [0, Mtot), W1/W3 = shared-expert weights.
template <bool ROUTED>
__global__ void __launch_bounds__(256, 2)
gemm1_swiglu(const float* __restrict__ X,
             const float* __restrict__ W1,
             const float* __restrict__ W3,
             int Mtot) {
    int r0, r1;
    if (ROUTED) { int e = blockIdx.z; r0 = g_off[e]; r1 = g_off[e + 1]; }
    else        { r0 = 0; r1 = Mtot; }
    int mBase = r0 + blockIdx.x * 128;
    if (mBase >= r1) return;
    int n0 = blockIdx.y * 64;

    const float* w1 = W1;
    const float* w3 = W3;
    if (ROUTED) {
        size_t eoff = (size_t)blockIdx.z * DM * HID;
        w1 += eoff; w3 += eoff;
    }

    __shared__ __align__(16) float Xs[8][128];
    __shared__ __align__(16) float W1s[8][64];
    __shared__ __align__(16) float W3s[8][64];

    int tid = threadIdx.x;
    int tx = tid & 15, ty = tid >> 4;

    // X staging: thread loads float4 of row (tid>>1), k-half (tid&1)
    int mload = tid >> 1;
    int half  = tid & 1;
    int lslot = mBase + mload;
    bool lvalid = (lslot < r1);
    const float* xrow = X;
    if (lvalid) {
        int tok = ROUTED ? g_perm_tok[lslot] : lslot;
        xrow = X + (size_t)tok * DM + half * 4;
    }

    // W staging: tid<128 -> W1, tid>=128 -> W3; 8 k-rows x 16 float4 cols
    int wk = (tid & 127) >> 4;
    int wn = tid & 15;
    bool isW3 = (tid >= 128);
    const float* wsrc = (isW3 ? w3 : w1) + (size_t)wk * HID + n0 + wn * 4;

    float acc1[8][4], acc3[8][4];
    #pragma unroll
    for (int i = 0; i < 8; i++)
        #pragma unroll
        for (int j = 0; j < 4; j++) { acc1[i][j] = 0.f; acc3[i][j] = 0.f; }

    for (int k0 = 0; k0 < DM; k0 += 8) {
        float4 xv = lvalid ? *(const float4*)(xrow + k0)
                           : make_float4(0.f, 0.f, 0.f, 0.f);
        Xs[half * 4 + 0][mload] = xv.x;
        Xs[half * 4 + 1][mload] = xv.y;
        Xs[half * 4 + 2][mload] = xv.z;
        Xs[half * 4 + 3][mload] = xv.w;

        float4 wv = *(const float4*)(wsrc + (size_t)k0 * HID);
        if (isW3) *(float4*)&W3s[wk][wn * 4] = wv;
        else      *(float4*)&W1s[wk][wn * 4] = wv;
        __syncthreads();

        #pragma unroll
        for (int kk = 0; kk < 8; kk++) {
            float4 a0 = *(const float4*)&Xs[kk][ty * 4];
            float4 a1 = *(const float4*)&Xs[kk][64 + ty * 4];
            float4 b1 = *(const float4*)&W1s[kk][tx * 4];
            float4 b3 = *(const float4*)&W3s[kk][tx * 4];
            float a[8]  = {a0.x, a0.y, a0.z, a0.w, a1.x, a1.y, a1.z, a1.w};
            float p1[4] = {b1.x, b1.y, b1.z, b1.w};
            float p3[4] = {b3.x, b3.y, b3.z, b3.w};
            #pragma unroll
            for (int i = 0; i < 8; i++)
                #pragma unroll
                for (int j = 0; j < 4; j++) {
                    acc1[i][j] = fmaf(a[i], p1[j], acc1[i][j]);
                    acc3[i][j] = fmaf(a[i], p3[j], acc3[i][j]);
                }
        }
        __syncthreads();
    }

    // SwiGLU epilogue -> g_act[slot, n]
    #pragma unroll
    for (int i = 0; i < 8; i++) {
        int m = (i < 4) ? (ty * 4 + i) : (64 + ty * 4 + i - 4);
        int slot = mBase + m;
        if (slot < r1) {
            float v[4];
            #pragma unroll
            for (int j = 0; j < 4; j++) {
                float h1 = acc1[i][j], h3 = acc3[i][j];
                v[j] = (h1 / (1.f + expf(-h1))) * h3;   // silu(h1)*h3
            }
            *(float4*)&g_act[(size_t)slot * HID + n0 + tx * 4] =
                make_float4(v[0], v[1], v[2], v[3]);
        }
    }
}

// ---------------- GEMM2: Y = A * W2, 128x128 tile, 8x8 micro-tile ----------
// ROUTED: gate-scaled atomicAdd scatter into out[token]. !ROUTED: plain store.
template <bool ROUTED>
__global__ void __launch_bounds__(256, 2)
gemm2_comb(const float* __restrict__ W2,
           float* __restrict__ out,
           int Mtot) {
    int r0, r1;
    if (ROUTED) { int e = blockIdx.z; r0 = g_off[e]; r1 = g_off[e + 1]; }
    else        { r0 = 0; r1 = Mtot; }
    int mBase = r0 + blockIdx.x * 128;
    if (mBase >= r1) return;
    int n0 = blockIdx.y * 128;

    const float* w2 = W2;
    if (ROUTED) w2 += (size_t)blockIdx.z * HID * DM;

    __shared__ __align__(16) float As[8][128];
    __shared__ __align__(16) float Ws[8][128];

    int tid = threadIdx.x;
    int tx = tid & 15, ty = tid >> 4;
    int mload = tid >> 1, half = tid & 1;
    int lslot = mBase + mload;
    bool lvalid = (lslot < r1);
    size_t arow_off = (size_t)(lvalid ? lslot : r0) * HID + half * 4;

    int wk = tid >> 5, wn = tid & 31;   // 8 k-rows x 32 float4 cols
    const float* wptr = w2 + (size_t)wk * DM + n0 + wn * 4;

    float acc[8][8];
    #pragma unroll
    for (int i = 0; i < 8; i++)
        #pragma unroll
        for (int j = 0; j < 8; j++) acc[i][j] = 0.f;

    for (int k0 = 0; k0 < HID; k0 += 8) {
        float4 av = lvalid ? *(const float4*)&g_act[arow_off + k0]
                           : make_float4(0.f, 0.f, 0.f, 0.f);
        As[half * 4 + 0][mload] = av.x;
        As[half * 4 + 1][mload] = av.y;
        As[half * 4 + 2][mload] = av.z;
        As[half * 4 + 3][mload] = av.w;

        float4 wv = *(const float4*)(wptr + (size_t)k0 * DM);
        *(float4*)&Ws[wk][wn * 4] = wv;
        __syncthreads();

        #pragma unroll
        for (int kk = 0; kk < 8; kk++) {
            float4 a0 = *(const float4*)&As[kk][ty * 4];
            float4 a1 = *(const float4*)&As[kk][64 + ty * 4];
            float4 b0 = *(const float4*)&Ws[kk][tx * 4];
            float4 b1 = *(const float4*)&Ws[kk][64 + tx * 4];
            float a[8] = {a0.x, a0.y, a0.z, a0.w, a1.x, a1.y, a1.z, a1.w};
            float b[8] = {b0.x, b0.y, b0.z, b0.w, b1.x, b1.y, b1.z, b1.w};
            #pragma unroll
            for (int i = 0; i < 8; i++)
                #pragma unroll
                for (int j = 0; j < 8; j++)
                    acc[i][j] = fmaf(a[i], b[j], acc[i][j]);
        }
        __syncthreads();
    }

    #pragma unroll
    for (int i = 0; i < 8; i++) {
        int m = (i < 4) ? (ty * 4 + i) : (64 + ty * 4 + i - 4);
        int slot = mBase + m;
        if (slot >= r1) continue;
        if (ROUTED) {
            int tok  = g_perm_tok[slot];
            float g  = g_perm_gate[slot];
            float* dst = out + (size_t)tok * DM + n0;
            #pragma unroll
            for (int j = 0; j < 8; j++) {
                int c = (j < 4) ? (tx * 4 + j) : (64 + tx * 4 + j - 4);
                atomicAdd(dst + c, g * acc[i][j]);
            }
        } else {
            float* dst = out + (size_t)slot * DM + n0;
            *(float4*)(dst + tx * 4) =
                make_float4(acc[i][0], acc[i][1], acc[i][2], acc[i][3]);
            *(float4*)(dst + 64 + tx * 4) =
                make_float4(acc[i][4], acc[i][5], acc[i][6], acc[i][7]);
        }
    }
}

// ---------------- launch ----------------
extern "C" void kernel_launch(void* const* d_in, const int* in_sizes, int n_in,
                              void* d_out, int out_size) {
    (void)in_sizes; (void)n_in; (void)out_size;
    const float* x   = (const float*)d_in[0];
    const float* wr  = (const float*)d_in[1];
    const float* w1  = (const float*)d_in[2];
    const float* w3  = (const float*)d_in[3];
    const float* w2  = (const float*)d_in[4];
    const float* sw1 = (const float*)d_in[5];
    const float* sw3 = (const float*)d_in[6];
    const float* sw2 = (const float*)d_in[7];
    float* out = (float*)d_out;

    // Routing
    zero_counts_kernel<<<1, 32>>>();
    router_kernel<<<T_TOK, 256>>>(x, wr);
    scan_kernel<<<1, 32>>>();
    scatter_kernel<<<(T_TOK + 255) / 256, 256>>>();

    // Shared expert first (writes every out element -> covers 0xAA poison)
    gemm1_swiglu<false><<<dim3(T_TOK / 128, HID / 64, 1), 256>>>(x, sw1, sw3, T_TOK);
    gemm2_comb<false><<<dim3(T_TOK / 128, DM / 128, 1), 256>>>(sw2, out, T_TOK);

    // Routed experts (reuse g_act scratch; stream order guarantees safety)
    gemm1_swiglu<true><<<dim3(NSLOTS / 128, HID / 64, NE), 256>>>(x, w1, w3, 0);
    gemm2_comb<true><<<dim3(NSLOTS / 128, DM / 128, NE), 256>>>(w2, out, 0);
}

// round 15
// speedup vs baseline: 1.4237x; 1.4233x over previous
#include <cuda_runtime.h>
#include <cuda_bf16.h>
#include <mma.h>
#include <math.h>
#include <stdint.h>

using namespace nvcuda;

// ---------------- problem constants ----------------
#define T_TOK   4096
#define DM      1024
#define HID     2048
#define NE      8
#define NSLOTS  (T_TOK * 2)

// ---------------- device scratch (zero-init, no runtime allocation) ----------------
__device__ __align__(16) float g_act[(size_t)NSLOTS * HID];   // SwiGLU act fp32 (64MB)
__device__ int   g_cnt[NE];
__device__ int   g_off[NE + 1];
__device__ int   g_cursor[NE];
__device__ int   g_top_e[NSLOTS];
__device__ float g_top_g[NSLOTS];
__device__ int   g_perm_tok[NSLOTS];
__device__ float g_perm_gate[NSLOTS];

// split v = hi + lo (bf16 each); captures fp32 value to ~2^-18 relative
static __device__ __forceinline__ void moe_split2(float a, float b,
        __nv_bfloat16* __restrict__ hp, __nv_bfloat16* __restrict__ lp) {
    __nv_bfloat162 h = __floats2bfloat162_rn(a, b);
    __nv_bfloat162 l = __floats2bfloat162_rn(a - __bfloat162float(h.x),
                                             b - __bfloat162float(h.y));
    *(__nv_bfloat162*)hp = h;
    *(__nv_bfloat162*)lp = l;
}

// ---------------- routing kernels (verbatim from passing R7) ----------------
__global__ void moe_zero_counts() { if (threadIdx.x < NE) g_cnt[threadIdx.x] = 0; }

__global__ void moe_router(const float* __restrict__ x, const float* __restrict__ wr) {
    int t = blockIdx.x, tid = threadIdx.x;
    int w = tid >> 5, lane = tid & 31;
    const float* xr = x + (size_t)t * DM;
    float partial = 0.f;
    for (int d = lane; d < DM; d += 32) partial += xr[d] * wr[d * NE + w];
    #pragma unroll
    for (int o = 16; o; o >>= 1) partial += __shfl_xor_sync(0xffffffffu, partial, o);
    __shared__ float logits[NE];
    if (lane == 0) logits[w] = partial;
    __syncthreads();
    if (tid == 0) {
        float mx = logits[0];
        #pragma unroll
        for (int e = 1; e < NE; e++) mx = fmaxf(mx, logits[e]);
        float p[NE];
        #pragma unroll
        for (int e = 0; e < NE; e++) p[e] = expf(logits[e] - mx);
        int e0 = 0;
        #pragma unroll
        for (int e = 1; e < NE; e++) if (p[e] > p[e0]) e0 = e;
        int e1 = (e0 == 0) ? 1 : 0;
        #pragma unroll
        for (int e = 0; e < NE; e++) if (e != e0 && p[e] > p[e1]) e1 = e;
        float s2 = p[e0] + p[e1];
        g_top_e[2*t]   = e0; g_top_g[2*t]   = p[e0] / s2;
        g_top_e[2*t+1] = e1; g_top_g[2*t+1] = p[e1] / s2;
        atomicAdd(&g_cnt[e0], 1);
        atomicAdd(&g_cnt[e1], 1);
    }
}

__global__ void moe_scan() {
    if (threadIdx.x == 0) {
        int acc = 0;
        for (int e = 0; e < NE; e++) { g_off[e] = acc; acc += g_cnt[e]; g_cursor[e] = 0; }
        g_off[NE] = acc;
    }
}

__global__ void moe_scatter() {
    int t = blockIdx.x * blockDim.x + threadIdx.x;
    if (t >= T_TOK) return;
    #pragma unroll
    for (int k = 0; k < 2; k++) {
        int e = g_top_e[2*t + k];
        int pos = g_off[e] + atomicAdd(&g_cursor[e], 1);
        g_perm_tok[pos]  = t;
        g_perm_gate[pos] = g_top_g[2*t + k];
    }
}

// ---------------- GEMM1: act = silu(Xg@W1) * (Xg@W3), split-bf16 wmma ----------------
// Tile 128x64, K-chunk 32, 8 warps (4m x 2n), warp tile 32x32 (2x2 frags).
// fp32 inputs split hi/lo inline during smem staging; D = Ah*Bh + Ah*Bl + Al*Bh.
// smem: Ah[128][40]@0  Al@10240  B1h[32][72]@20480  B1l@25088  B3h@29696  B3l@34304
//       total 38912B; epilogue reuses base as fp32 [128][68] (34816B).
template <bool ROUTED>
__global__ void __launch_bounds__(256) moe_g1(const float* __restrict__ X,
                                              const float* __restrict__ W1base,
                                              const float* __restrict__ W3base,
                                              int Mtot) {
    int r0, r1, eidx = 0;
    if (ROUTED) { eidx = blockIdx.z; r0 = g_off[eidx]; r1 = g_off[eidx + 1]; }
    else        { r0 = 0; r1 = Mtot; }
    int mBase = r0 + blockIdx.x * 128;
    if (mBase >= r1) return;
    int n0 = blockIdx.y * 64;
    const float* w1 = W1base + (ROUTED ? (size_t)eidx * DM * HID : 0);
    const float* w3 = W3base + (ROUTED ? (size_t)eidx * DM * HID : 0);

    __shared__ __align__(16) char smem[38912];
    __nv_bfloat16* Ah  = (__nv_bfloat16*)smem;                 // [128][40]
    __nv_bfloat16* Al  = (__nv_bfloat16*)(smem + 10240);
    __nv_bfloat16* B1h = (__nv_bfloat16*)(smem + 20480);       // [32][72]
    __nv_bfloat16* B1l = (__nv_bfloat16*)(smem + 25088);
    __nv_bfloat16* B3h = (__nv_bfloat16*)(smem + 29696);
    __nv_bfloat16* B3l = (__nv_bfloat16*)(smem + 34304);

    int tid = threadIdx.x, wid = tid >> 5;
    int warpM = (wid & 3) * 32, warpN = (wid >> 2) * 32;

    // staging roles
    int ar = tid >> 1, ac = (tid & 1) * 16;        // A: 2 thr/row, 16 floats each
    const float* aP;
    {
        int s = mBase + ar; if (s >= r1) s = r1 - 1;
        int tok = ROUTED ? g_perm_tok[s] : s;
        aP = X + (size_t)tok * DM + ac;
    }
    int br = tid >> 3, bc = (tid & 7) * 8;         // B: 8 thr/k-row, 8 floats each
    const float* b1P = w1 + (size_t)br * HID + n0 + bc;
    const float* b3P = w3 + (size_t)br * HID + n0 + bc;

    wmma::fragment<wmma::accumulator, 16, 16, 16, float> c1[2][2], c3[2][2];
    #pragma unroll
    for (int mi = 0; mi < 2; mi++)
        #pragma unroll
        for (int ni = 0; ni < 2; ni++) {
            wmma::fill_fragment(c1[mi][ni], 0.f);
            wmma::fill_fragment(c3[mi][ni], 0.f);
        }

    float4 aR[4], b1R[2], b3R[2];
    const int Ksteps = DM / 32;   // 32

    // prefetch + stage chunk 0
    #pragma unroll
    for (int j = 0; j < 4; j++) aR[j] = *(const float4*)(aP + 4 * j);
    #pragma unroll
    for (int j = 0; j < 2; j++) {
        b1R[j] = *(const float4*)(b1P + 4 * j);
        b3R[j] = *(const float4*)(b3P + 4 * j);
    }
    {
        __nv_bfloat16* ah = Ah + ar * 40 + ac;
        __nv_bfloat16* al = Al + ar * 40 + ac;
        #pragma unroll
        for (int j = 0; j < 4; j++) {
            moe_split2(aR[j].x, aR[j].y, ah + 4*j,     al + 4*j);
            moe_split2(aR[j].z, aR[j].w, ah + 4*j + 2, al + 4*j + 2);
        }
        __nv_bfloat16* b1h = B1h + br * 72 + bc;
        __nv_bfloat16* b1l = B1l + br * 72 + bc;
        __nv_bfloat16* b3h = B3h + br * 72 + bc;
        __nv_bfloat16* b3l = B3l + br * 72 + bc;
        #pragma unroll
        for (int j = 0; j < 2; j++) {
            moe_split2(b1R[j].x, b1R[j].y, b1h + 4*j,     b1l + 4*j);
            moe_split2(b1R[j].z, b1R[j].w, b1h + 4*j + 2, b1l + 4*j + 2);
            moe_split2(b3R[j].x, b3R[j].y, b3h + 4*j,     b3l + 4*j);
            moe_split2(b3R[j].z, b3R[j].w, b3h + 4*j + 2, b3l + 4*j + 2);
        }
    }
    __syncthreads();

    for (int k = 0; k < Ksteps; k++) {
        // prefetch next chunk into registers (overlaps with wmma below)
        if (k + 1 < Ksteps) {
            int k0 = (k + 1) * 32;
            #pragma unroll
            for (int j = 0; j < 4; j++) aR[j] = *(const float4*)(aP + k0 + 4 * j);
            #pragma unroll
            for (int j = 0; j < 2; j++) {
                b1R[j] = *(const float4*)(b1P + (size_t)k0 * HID + 4 * j);
                b3R[j] = *(const float4*)(b3P + (size_t)k0 * HID + 4 * j);
            }
        }

        #pragma unroll
        for (int kf = 0; kf < 2; kf++) {
            wmma::fragment<wmma::matrix_a, 16, 16, 16, __nv_bfloat16, wmma::row_major> afh[2], afl[2];
            wmma::fragment<wmma::matrix_b, 16, 16, 16, __nv_bfloat16, wmma::row_major> bh[2], bl[2];
            #pragma unroll
            for (int mi = 0; mi < 2; mi++) {
                wmma::load_matrix_sync(afh[mi], Ah + (warpM + mi * 16) * 40 + kf * 16, 40);
                wmma::load_matrix_sync(afl[mi], Al + (warpM + mi * 16) * 40 + kf * 16, 40);
            }
            // W1 pass
            #pragma unroll
            for (int ni = 0; ni < 2; ni++) {
                wmma::load_matrix_sync(bh[ni], B1h + kf * 16 * 72 + warpN + ni * 16, 72);
                wmma::load_matrix_sync(bl[ni], B1l + kf * 16 * 72 + warpN + ni * 16, 72);
            }
            #pragma unroll
            for (int mi = 0; mi < 2; mi++)
                #pragma unroll
                for (int ni = 0; ni < 2; ni++) {
                    wmma::mma_sync(c1[mi][ni], afh[mi], bh[ni], c1[mi][ni]);
                    wmma::mma_sync(c1[mi][ni], afh[mi], bl[ni], c1[mi][ni]);
                    wmma::mma_sync(c1[mi][ni], afl[mi], bh[ni], c1[mi][ni]);
                }
            // W3 pass
            #pragma unroll
            for (int ni = 0; ni < 2; ni++) {
                wmma::load_matrix_sync(bh[ni], B3h + kf * 16 * 72 + warpN + ni * 16, 72);
                wmma::load_matrix_sync(bl[ni], B3l + kf * 16 * 72 + warpN + ni * 16, 72);
            }
            #pragma unroll
            for (int mi = 0; mi < 2; mi++)
                #pragma unroll
                for (int ni = 0; ni < 2; ni++) {
                    wmma::mma_sync(c3[mi][ni], afh[mi], bh[ni], c3[mi][ni]);
                    wmma::mma_sync(c3[mi][ni], afh[mi], bl[ni], c3[mi][ni]);
                    wmma::mma_sync(c3[mi][ni], afl[mi], bh[ni], c3[mi][ni]);
                }
        }
        __syncthreads();

        // stage prefetched chunk
        if (k + 1 < Ksteps) {
            __nv_bfloat16* ah = Ah + ar * 40 + ac;
            __nv_bfloat16* al = Al + ar * 40 + ac;
            #pragma unroll
            for (int j = 0; j < 4; j++) {
                moe_split2(aR[j].x, aR[j].y, ah + 4*j,     al + 4*j);
                moe_split2(aR[j].z, aR[j].w, ah + 4*j + 2, al + 4*j + 2);
            }
            __nv_bfloat16* b1h = B1h + br * 72 + bc;
            __nv_bfloat16* b1l = B1l + br * 72 + bc;
            __nv_bfloat16* b3h = B3h + br * 72 + bc;
            __nv_bfloat16* b3l = B3l + br * 72 + bc;
            #pragma unroll
            for (int j = 0; j < 2; j++) {
                moe_split2(b1R[j].x, b1R[j].y, b1h + 4*j,     b1l + 4*j);
                moe_split2(b1R[j].z, b1R[j].w, b1h + 4*j + 2, b1l + 4*j + 2);
                moe_split2(b3R[j].x, b3R[j].y, b3h + 4*j,     b3l + 4*j);
                moe_split2(b3R[j].z, b3R[j].w, b3h + 4*j + 2, b3l + 4*j + 2);
            }
            __syncthreads();
        }
    }

    // epilogue: SwiGLU elementwise on identical-layout accumulators, via smem fp32
    float* Sf = (float*)smem;   // [128][68]
    #pragma unroll
    for (int mi = 0; mi < 2; mi++)
        #pragma unroll
        for (int ni = 0; ni < 2; ni++) {
            #pragma unroll
            for (int e = 0; e < c1[mi][ni].num_elements; e++) {
                float h1 = c1[mi][ni].x[e], h3 = c3[mi][ni].x[e];
                c1[mi][ni].x[e] = h1 * h3 / (1.f + __expf(-h1));
            }
            wmma::store_matrix_sync(Sf + (warpM + mi * 16) * 68 + (warpN + ni * 16),
                                    c1[mi][ni], 68, wmma::mem_row_major);
        }
    __syncthreads();

    {
        int row = tid >> 1, cb = (tid & 1) * 32;
        int slot = mBase + row;
        if (slot < r1) {
            const float* s = Sf + row * 68 + cb;
            float* dst = g_act + (size_t)slot * HID + n0 + cb;
            #pragma unroll
            for (int j = 0; j < 8; j++)
                *(float4*)(dst + 4*j) = *(const float4*)(s + 4*j);
        }
    }
}

// ---------------- GEMM2: Y = act @ W2 (+combine), split-bf16 wmma ----------------
// Tile 128x64, warp tile 32x32. A = g_act fp32, B = w2 fp32 [HID][DM] row-major.
// smem: Ah[128][40]@0  Al@10240  Bh[32][72]@20480  Bl@25088 (29696B);
//       epilogue fp32 [128][68] = 34816B -> smem size 34816.
template <bool ROUTED>
__global__ void __launch_bounds__(256) moe_g2(const float* __restrict__ W2base,
                                              float* __restrict__ out, int Mtot) {
    int r0, r1, eidx = 0;
    if (ROUTED) { eidx = blockIdx.z; r0 = g_off[eidx]; r1 = g_off[eidx + 1]; }
    else        { r0 = 0; r1 = Mtot; }
    int mBase = r0 + blockIdx.x * 128;
    if (mBase >= r1) return;
    int n0 = blockIdx.y * 64;
    const float* w2 = W2base + (ROUTED ? (size_t)eidx * HID * DM : 0);

    __shared__ __align__(16) char smem[34816];
    __nv_bfloat16* Ah = (__nv_bfloat16*)smem;                 // [128][40]
    __nv_bfloat16* Al = (__nv_bfloat16*)(smem + 10240);
    __nv_bfloat16* Bh = (__nv_bfloat16*)(smem + 20480);       // [32][72]
    __nv_bfloat16* Bl = (__nv_bfloat16*)(smem + 25088);

    int tid = threadIdx.x, wid = tid >> 5;
    int warpM = (wid & 3) * 32, warpN = (wid >> 2) * 32;

    int ar = tid >> 1, ac = (tid & 1) * 16;
    const float* aP;
    {
        int s = mBase + ar; if (s >= r1) s = r1 - 1;
        aP = g_act + (size_t)s * HID + ac;
    }
    int br = tid >> 3, bc = (tid & 7) * 8;
    const float* bP = w2 + (size_t)br * DM + n0 + bc;

    wmma::fragment<wmma::accumulator, 16, 16, 16, float> acc[2][2];
    #pragma unroll
    for (int mi = 0; mi < 2; mi++)
        #pragma unroll
        for (int ni = 0; ni < 2; ni++) wmma::fill_fragment(acc[mi][ni], 0.f);

    float4 aR[4], bR[2];
    const int Ksteps = HID / 32;   // 64

    #pragma unroll
    for (int j = 0; j < 4; j++) aR[j] = *(const float4*)(aP + 4 * j);
    bR[0] = *(const float4*)(bP);
    bR[1] = *(const float4*)(bP + 4);
    {
        __nv_bfloat16* ah = Ah + ar * 40 + ac;
        __nv_bfloat16* al = Al + ar * 40 + ac;
        #pragma unroll
        for (int j = 0; j < 4; j++) {
            moe_split2(aR[j].x, aR[j].y, ah + 4*j,     al + 4*j);
            moe_split2(aR[j].z, aR[j].w, ah + 4*j + 2, al + 4*j + 2);
        }
        __nv_bfloat16* bh = Bh + br * 72 + bc;
        __nv_bfloat16* bl = Bl + br * 72 + bc;
        #pragma unroll
        for (int j = 0; j < 2; j++) {
            moe_split2(bR[j].x, bR[j].y, bh + 4*j,     bl + 4*j);
            moe_split2(bR[j].z, bR[j].w, bh + 4*j + 2, bl + 4*j + 2);
        }
    }
    __syncthreads();

    for (int k = 0; k < Ksteps; k++) {
        if (k + 1 < Ksteps) {
            int k0 = (k + 1) * 32;
            #pragma unroll
            for (int j = 0; j < 4; j++) aR[j] = *(const float4*)(aP + k0 + 4 * j);
            bR[0] = *(const float4*)(bP + (size_t)k0 * DM);
            bR[1] = *(const float4*)(bP + (size_t)k0 * DM + 4);
        }

        #pragma unroll
        for (int kf = 0; kf < 2; kf++) {
            wmma::fragment<wmma::matrix_a, 16, 16, 16, __nv_bfloat16, wmma::row_major> afh[2], afl[2];
            wmma::fragment<wmma::matrix_b, 16, 16, 16, __nv_bfloat16, wmma::row_major> bfh[2], bfl[2];
            #pragma unroll
            for (int mi = 0; mi < 2; mi++) {
                wmma::load_matrix_sync(afh[mi], Ah + (warpM + mi * 16) * 40 + kf * 16, 40);
                wmma::load_matrix_sync(afl[mi], Al + (warpM + mi * 16) * 40 + kf * 16, 40);
            }
            #pragma unroll
            for (int ni = 0; ni < 2; ni++) {
                wmma::load_matrix_sync(bfh[ni], Bh + kf * 16 * 72 + warpN + ni * 16, 72);
                wmma::load_matrix_sync(bfl[ni], Bl + kf * 16 * 72 + warpN + ni * 16, 72);
            }
            #pragma unroll
            for (int mi = 0; mi < 2; mi++)
                #pragma unroll
                for (int ni = 0; ni < 2; ni++) {
                    wmma::mma_sync(acc[mi][ni], afh[mi], bfh[ni], acc[mi][ni]);
                    wmma::mma_sync(acc[mi][ni], afh[mi], bfl[ni], acc[mi][ni]);
                    wmma::mma_sync(acc[mi][ni], afl[mi], bfh[ni], acc[mi][ni]);
                }
        }
        __syncthreads();

        if (k + 1 < Ksteps) {
            __nv_bfloat16* ah = Ah + ar * 40 + ac;
            __nv_bfloat16* al = Al + ar * 40 + ac;
            #pragma unroll
            for (int j = 0; j < 4; j++) {
                moe_split2(aR[j].x, aR[j].y, ah + 4*j,     al + 4*j);
                moe_split2(aR[j].z, aR[j].w, ah + 4*j + 2, al + 4*j + 2);
            }
            __nv_bfloat16* bh = Bh + br * 72 + bc;
            __nv_bfloat16* bl = Bl + br * 72 + bc;
            #pragma unroll
            for (int j = 0; j < 2; j++) {
                moe_split2(bR[j].x, bR[j].y, bh + 4*j,     bl + 4*j);
                moe_split2(bR[j].z, bR[j].w, bh + 4*j + 2, bl + 4*j + 2);
            }
            __syncthreads();
        }
    }

    // epilogue through smem fp32
    float* Sf = (float*)smem;   // [128][68]
    #pragma unroll
    for (int mi = 0; mi < 2; mi++)
        #pragma unroll
        for (int ni = 0; ni < 2; ni++)
            wmma::store_matrix_sync(Sf + (warpM + mi * 16) * 68 + (warpN + ni * 16),
                                    acc[mi][ni], 68, wmma::mem_row_major);
    __syncthreads();

    {
        int row = tid >> 1, cb = (tid & 1) * 32;
        int slot = mBase + row;
        if (slot < r1) {
            const float* s = Sf + row * 68 + cb;
            if (ROUTED) {
                int tok = g_perm_tok[slot];
                float g = g_perm_gate[slot];
                float* dst = out + (size_t)tok * DM + n0 + cb;
                #pragma unroll
                for (int j = 0; j < 32; j++) atomicAdd(dst + j, g * s[j]);
            } else {
                float* dst = out + (size_t)slot * DM + n0 + cb;
                #pragma unroll
                for (int j = 0; j < 8; j++)
                    *(float4*)(dst + 4*j) = *(const float4*)(s + 4*j);
            }
        }
    }
}

// ---------------- launch ----------------
extern "C" void kernel_launch(void* const* d_in, const int* in_sizes, int n_in,
                              void* d_out, int out_size) {
    (void)in_sizes; (void)n_in; (void)out_size;
    const float* x   = (const float*)d_in[0];
    const float* wr  = (const float*)d_in[1];
    const float* w1  = (const float*)d_in[2];
    const float* w3  = (const float*)d_in[3];
    const float* w2  = (const float*)d_in[4];
    const float* sw1 = (const float*)d_in[5];
    const float* sw3 = (const float*)d_in[6];
    const float* sw2 = (const float*)d_in[7];
    float* out = (float*)d_out;

    // Routing
    moe_zero_counts<<<1, 32>>>();
    moe_router<<<T_TOK, 256>>>(x, wr);
    moe_scan<<<1, 32>>>();
    moe_scatter<<<(T_TOK + 255) / 256, 256>>>();

    // Shared expert first (plain stores cover the 0xAA poison in out)
    moe_g1<false><<<dim3(T_TOK / 128, HID / 64, 1), 256>>>(x, sw1, sw3, T_TOK);
    moe_g2<false><<<dim3(T_TOK / 128, DM / 64, 1), 256>>>(sw2, out, T_TOK);

    // Routed experts (worst-case grid; empty tiles early-exit)
    moe_g1<true><<<dim3(NSLOTS / 128, HID / 64, NE), 256>>>(x, w1, w3, 0);
    moe_g2<true><<<dim3(NSLOTS / 128, DM / 64, NE), 256>>>(w2, out, 0);
}

// round 16
// speedup vs baseline: 1.6531x; 1.1611x over previous
#include <cuda_runtime.h>
#include <cuda_bf16.h>
#include <mma.h>
#include <math.h>
#include <stdint.h>

using namespace nvcuda;

// ---------------- problem constants ----------------
#define T_TOK   4096
#define DM      1024
#define HID     2048
#define NE      8
#define NSLOTS  (T_TOK * 2)

// ---------------- device scratch (zero-init, no runtime allocation) ----------------
__device__ __align__(16) __nv_bfloat16 g_xh[(size_t)T_TOK * DM];
__device__ __align__(16) __nv_bfloat16 g_xl[(size_t)T_TOK * DM];
__device__ __align__(16) __nv_bfloat16 g_w1h[(size_t)NE * DM * HID];
__device__ __align__(16) __nv_bfloat16 g_w1l[(size_t)NE * DM * HID];
__device__ __align__(16) __nv_bfloat16 g_w3h[(size_t)NE * DM * HID];
__device__ __align__(16) __nv_bfloat16 g_w3l[(size_t)NE * DM * HID];
__device__ __align__(16) __nv_bfloat16 g_w2h[(size_t)NE * HID * DM];
__device__ __align__(16) __nv_bfloat16 g_w2l[(size_t)NE * HID * DM];
__device__ __align__(16) __nv_bfloat16 g_s1h[(size_t)DM * HID];
__device__ __align__(16) __nv_bfloat16 g_s1l[(size_t)DM * HID];
__device__ __align__(16) __nv_bfloat16 g_s3h[(size_t)DM * HID];
__device__ __align__(16) __nv_bfloat16 g_s3l[(size_t)DM * HID];
__device__ __align__(16) __nv_bfloat16 g_s2h[(size_t)HID * DM];
__device__ __align__(16) __nv_bfloat16 g_s2l[(size_t)HID * DM];
__device__ __align__(16) __nv_bfloat16 g_acth[(size_t)NSLOTS * HID];
__device__ __align__(16) __nv_bfloat16 g_actl[(size_t)NSLOTS * HID];
__device__ int   g_cnt[NE];
__device__ int   g_off[NE + 1];
__device__ int   g_cursor[NE];
__device__ int   g_top_e[NSLOTS];
__device__ float g_top_g[NSLOTS];
__device__ int   g_perm_tok[NSLOTS];
__device__ float g_perm_gate[NSLOTS];

// ---------------- helpers ----------------
static __device__ __forceinline__ uint32_t moe_smem_u32(const void* p) {
    uint32_t a;
    asm("{ .reg .u64 t; cvta.to.shared.u64 t, %1; cvt.u32.u64 %0, t; }" : "=r"(a) : "l"(p));
    return a;
}
static __device__ __forceinline__ void moe_cp16(uint32_t dst, const void* src) {
    asm volatile("cp.async.cg.shared.global [%0], [%1], 16;" :: "r"(dst), "l"(src));
}
#define MOE_CP_COMMIT() asm volatile("cp.async.commit_group;" ::: "memory")
#define MOE_CP_WAIT0()  asm volatile("cp.async.wait_group 0;" ::: "memory")

// split v = hi + lo (bf16 each)
static __device__ __forceinline__ void moe_split2(float a, float b,
        __nv_bfloat16* __restrict__ hp, __nv_bfloat16* __restrict__ lp) {
    __nv_bfloat162 h = __floats2bfloat162_rn(a, b);
    __nv_bfloat162 l = __floats2bfloat162_rn(a - __bfloat162float(h.x),
                                             b - __bfloat162float(h.y));
    *(__nv_bfloat162*)hp = h;
    *(__nv_bfloat162*)lp = l;
}

// ---------------- routing kernels (verbatim, proven) ----------------
__global__ void moe_zero_counts() { if (threadIdx.x < NE) g_cnt[threadIdx.x] = 0; }

__global__ void moe_router(const float* __restrict__ x, const float* __restrict__ wr) {
    int t = blockIdx.x, tid = threadIdx.x;
    int w = tid >> 5, lane = tid & 31;
    const float* xr = x + (size_t)t * DM;
    float partial = 0.f;
    for (int d = lane; d < DM; d += 32) partial += xr[d] * wr[d * NE + w];
    #pragma unroll
    for (int o = 16; o; o >>= 1) partial += __shfl_xor_sync(0xffffffffu, partial, o);
    __shared__ float logits[NE];
    if (lane == 0) logits[w] = partial;
    __syncthreads();
    if (tid == 0) {
        float mx = logits[0];
        #pragma unroll
        for (int e = 1; e < NE; e++) mx = fmaxf(mx, logits[e]);
        float p[NE];
        #pragma unroll
        for (int e = 0; e < NE; e++) p[e] = expf(logits[e] - mx);
        int e0 = 0;
        #pragma unroll
        for (int e = 1; e < NE; e++) if (p[e] > p[e0]) e0 = e;
        int e1 = (e0 == 0) ? 1 : 0;
        #pragma unroll
        for (int e = 0; e < NE; e++) if (e != e0 && p[e] > p[e1]) e1 = e;
        float s2 = p[e0] + p[e1];
        g_top_e[2*t]   = e0; g_top_g[2*t]   = p[e0] / s2;
        g_top_e[2*t+1] = e1; g_top_g[2*t+1] = p[e1] / s2;
        atomicAdd(&g_cnt[e0], 1);
        atomicAdd(&g_cnt[e1], 1);
    }
}

__global__ void moe_scan() {
    if (threadIdx.x == 0) {
        int acc = 0;
        for (int e = 0; e < NE; e++) { g_off[e] = acc; acc += g_cnt[e]; g_cursor[e] = 0; }
        g_off[NE] = acc;
    }
}

__global__ void moe_scatter() {
    int t = blockIdx.x * blockDim.x + threadIdx.x;
    if (t >= T_TOK) return;
    #pragma unroll
    for (int k = 0; k < 2; k++) {
        int e = g_top_e[2*t + k];
        int pos = g_off[e] + atomicAdd(&g_cursor[e], 1);
        g_perm_tok[pos]  = t;
        g_perm_gate[pos] = g_top_g[2*t + k];
    }
}

// ---------------- pre-pass: fp32 -> bf16 hi/lo split ----------------
__global__ void moe_split_kernel(const float* __restrict__ src,
                                 __nv_bfloat16* __restrict__ h,
                                 __nv_bfloat16* __restrict__ l) {
    size_t i = ((size_t)blockIdx.x * blockDim.x + threadIdx.x) * 4;
    float4 v = *(const float4*)(src + i);
    __nv_bfloat162 h0 = __floats2bfloat162_rn(v.x, v.y);
    __nv_bfloat162 h1 = __floats2bfloat162_rn(v.z, v.w);
    __nv_bfloat162 l0 = __floats2bfloat162_rn(v.x - __bfloat162float(h0.x),
                                              v.y - __bfloat162float(h0.y));
    __nv_bfloat162 l1 = __floats2bfloat162_rn(v.z - __bfloat162float(h1.x),
                                              v.w - __bfloat162float(h1.y));
    uint2 hu, lu;
    hu.x = *(uint32_t*)&h0; hu.y = *(uint32_t*)&h1;
    lu.x = *(uint32_t*)&l0; lu.y = *(uint32_t*)&l1;
    *(uint2*)(h + i) = hu;
    *(uint2*)(l + i) = lu;
}

// ==========================================================================
// GEMM1: act = silu(Xg@W1) * (Xg@W3), split-bf16 wmma, cp.async double-buffer
// Tile 128x64, K-chunk 16, 8 warps (4m x 2n), warp tile 32x32.
// Stage (21504B): Ah[128][24]b16@0  Al@6144  B1h[16][72]@12288  B1l@14592
//                 B3h@16896  B3l@19200.  2 stages = 43008B static smem.
// A rows padded to 48B, B rows to 144B -> conflict-free ldmatrix.
// ==========================================================================
template <bool ROUTED>
__global__ void __launch_bounds__(256) moe_g1(
        const __nv_bfloat16* __restrict__ W1h, const __nv_bfloat16* __restrict__ W1l,
        const __nv_bfloat16* __restrict__ W3h, const __nv_bfloat16* __restrict__ W3l,
        int Mtot) {
    int r0, r1;
    if (ROUTED) {
        int eidx = blockIdx.z; r0 = g_off[eidx]; r1 = g_off[eidx + 1];
        size_t eo = (size_t)eidx * DM * HID;
        W1h += eo; W1l += eo; W3h += eo; W3l += eo;
    } else { r0 = 0; r1 = Mtot; }
    int mBase = r0 + blockIdx.x * 128;
    if (mBase >= r1) return;
    int n0 = blockIdx.y * 64;

    __shared__ __align__(16) char smem[43008];
    uint32_t sb = moe_smem_u32(smem);

    int tid = threadIdx.x, wid = tid >> 5;
    int warpM = (wid & 3) * 32, warpN = (wid >> 2) * 32;

    // A loader: 2 thr/row, one 16B chunk (8 bf16) each, per h/l
    int ar = tid >> 1, ac = tid & 1;
    const __nv_bfloat16 *aH, *aL;
    {
        int s = mBase + ar; if (s >= r1) s = r1 - 1;
        int tok = ROUTED ? g_perm_tok[s] : s;
        aH = g_xh + (size_t)tok * DM + ac * 8;
        aL = g_xl + (size_t)tok * DM + ac * 8;
    }
    uint32_t dA = (uint32_t)ar * 48 + ac * 16;

    // B loader: sel over {W1h,W1l,W3h,W3l}, 64 thr each: 16 k-rows x 4 col-quads
    int bsel = tid >> 6, bidx = tid & 63, brow = bidx >> 2, bq = bidx & 3;
    const __nv_bfloat16* bp = (bsel == 0) ? W1h : (bsel == 1) ? W1l
                            : (bsel == 2) ? W3h : W3l;
    const __nv_bfloat16* bB = bp + (size_t)brow * HID + n0 + bq * 16;
    uint32_t dB = 12288u + bsel * 2304 + brow * 144 + bq * 32;

    wmma::fragment<wmma::accumulator, 16, 16, 16, float> c1[2][2], c3[2][2];
    #pragma unroll
    for (int mi = 0; mi < 2; mi++)
        #pragma unroll
        for (int ni = 0; ni < 2; ni++) {
            wmma::fill_fragment(c1[mi][ni], 0.f);
            wmma::fill_fragment(c3[mi][ni], 0.f);
        }

    auto issue = [&](int k, int b) {
        uint32_t bb = sb + b * 21504;
        int k0 = k * 16;
        moe_cp16(bb + dA,        aH + k0);
        moe_cp16(bb + 6144 + dA, aL + k0);
        const __nv_bfloat16* s = bB + (size_t)k0 * HID;
        moe_cp16(bb + dB,      s);
        moe_cp16(bb + dB + 16, s + 8);
    };

    const int Ksteps = DM / 16;   // 64
    issue(0, 0); MOE_CP_COMMIT();
    MOE_CP_WAIT0(); __syncthreads();

    for (int k = 0; k < Ksteps; k++) {
        if (k + 1 < Ksteps) issue(k + 1, (k + 1) & 1);
        MOE_CP_COMMIT();

        const char* bb = smem + (k & 1) * 21504;
        const __nv_bfloat16* Ah  = (const __nv_bfloat16*)(bb);
        const __nv_bfloat16* Al  = (const __nv_bfloat16*)(bb + 6144);
        const __nv_bfloat16* B1h = (const __nv_bfloat16*)(bb + 12288);
        const __nv_bfloat16* B1l = (const __nv_bfloat16*)(bb + 14592);
        const __nv_bfloat16* B3h = (const __nv_bfloat16*)(bb + 16896);
        const __nv_bfloat16* B3l = (const __nv_bfloat16*)(bb + 19200);

        wmma::fragment<wmma::matrix_a, 16, 16, 16, __nv_bfloat16, wmma::row_major> afh[2], afl[2];
        wmma::fragment<wmma::matrix_b, 16, 16, 16, __nv_bfloat16, wmma::row_major> bh[2], bl[2];
        #pragma unroll
        for (int mi = 0; mi < 2; mi++) {
            wmma::load_matrix_sync(afh[mi], Ah + (warpM + mi * 16) * 24, 24);
            wmma::load_matrix_sync(afl[mi], Al + (warpM + mi * 16) * 24, 24);
        }
        #pragma unroll
        for (int ni = 0; ni < 2; ni++) {
            wmma::load_matrix_sync(bh[ni], B1h + warpN + ni * 16, 72);
            wmma::load_matrix_sync(bl[ni], B1l + warpN + ni * 16, 72);
        }
        #pragma unroll
        for (int mi = 0; mi < 2; mi++)
            #pragma unroll
            for (int ni = 0; ni < 2; ni++) {
                wmma::mma_sync(c1[mi][ni], afh[mi], bh[ni], c1[mi][ni]);
                wmma::mma_sync(c1[mi][ni], afh[mi], bl[ni], c1[mi][ni]);
                wmma::mma_sync(c1[mi][ni], afl[mi], bh[ni], c1[mi][ni]);
            }
        #pragma unroll
        for (int ni = 0; ni < 2; ni++) {
            wmma::load_matrix_sync(bh[ni], B3h + warpN + ni * 16, 72);
            wmma::load_matrix_sync(bl[ni], B3l + warpN + ni * 16, 72);
        }
        #pragma unroll
        for (int mi = 0; mi < 2; mi++)
            #pragma unroll
            for (int ni = 0; ni < 2; ni++) {
                wmma::mma_sync(c3[mi][ni], afh[mi], bh[ni], c3[mi][ni]);
                wmma::mma_sync(c3[mi][ni], afh[mi], bl[ni], c3[mi][ni]);
                wmma::mma_sync(c3[mi][ni], afl[mi], bh[ni], c3[mi][ni]);
            }

        MOE_CP_WAIT0(); __syncthreads();
    }

    // epilogue: SwiGLU elementwise on identical-layout accumulators, via smem fp32
    float* Sf = (float*)smem;   // [128][68] = 34816B
    #pragma unroll
    for (int mi = 0; mi < 2; mi++)
        #pragma unroll
        for (int ni = 0; ni < 2; ni++) {
            #pragma unroll
            for (int e = 0; e < c1[mi][ni].num_elements; e++) {
                float h1 = c1[mi][ni].x[e], h3 = c3[mi][ni].x[e];
                c1[mi][ni].x[e] = h1 * h3 / (1.f + __expf(-h1));
            }
            wmma::store_matrix_sync(Sf + (warpM + mi * 16) * 68 + (warpN + ni * 16),
                                    c1[mi][ni], 68, wmma::mem_row_major);
        }
    __syncthreads();

    {
        int row = tid >> 1, cb = (tid & 1) * 32;
        int slot = mBase + row;
        if (slot < r1) {
            const float* s = Sf + row * 68 + cb;
            __nv_bfloat16* dh = g_acth + (size_t)slot * HID + n0 + cb;
            __nv_bfloat16* dl = g_actl + (size_t)slot * HID + n0 + cb;
            #pragma unroll
            for (int j = 0; j < 16; j++)
                moe_split2(s[2*j], s[2*j + 1], dh + 2*j, dl + 2*j);
        }
    }
}

// ==========================================================================
// GEMM2: Y = act @ W2 (+combine). Tile 128x64, K-chunk 16, warp tile 32x32.
// Stage (16896B): Ah@0  Al@6144  Bh[16][72]@12288  Bl@14592.
// 2 stages = 33792B; epilogue fp32 [128][68] = 34816B -> smem 34816.
// ==========================================================================
template <bool ROUTED>
__global__ void __launch_bounds__(256) moe_g2(
        const __nv_bfloat16* __restrict__ W2h, const __nv_bfloat16* __restrict__ W2l,
        float* __restrict__ out, int Mtot) {
    int r0, r1;
    if (ROUTED) {
        int eidx = blockIdx.z; r0 = g_off[eidx]; r1 = g_off[eidx + 1];
        size_t eo = (size_t)eidx * HID * DM;
        W2h += eo; W2l += eo;
    } else { r0 = 0; r1 = Mtot; }
    int mBase = r0 + blockIdx.x * 128;
    if (mBase >= r1) return;
    int n0 = blockIdx.y * 64;

    __shared__ __align__(16) char smem[34816];
    uint32_t sb = moe_smem_u32(smem);

    int tid = threadIdx.x, wid = tid >> 5;
    int warpM = (wid & 3) * 32, warpN = (wid >> 2) * 32;

    int ar = tid >> 1, ac = tid & 1;
    const __nv_bfloat16 *aH, *aL;
    {
        int s = mBase + ar; if (s >= r1) s = r1 - 1;
        aH = g_acth + (size_t)s * HID + ac * 8;
        aL = g_actl + (size_t)s * HID + ac * 8;
    }
    uint32_t dA = (uint32_t)ar * 48 + ac * 16;

    // B loader: 2 arrays (h/l) x 128 thr: 16 k-rows x 8 col chunks, 1 chunk each
    int bsel = tid >> 7, bidx = tid & 127, brow = bidx >> 3, bq = bidx & 7;
    const __nv_bfloat16* bp = bsel ? W2l : W2h;
    const __nv_bfloat16* bB = bp + (size_t)brow * DM + n0 + bq * 8;
    uint32_t dB = 12288u + bsel * 2304 + brow * 144 + bq * 16;

    wmma::fragment<wmma::accumulator, 16, 16, 16, float> acc[2][2];
    #pragma unroll
    for (int mi = 0; mi < 2; mi++)
        #pragma unroll
        for (int ni = 0; ni < 2; ni++) wmma::fill_fragment(acc[mi][ni], 0.f);

    auto issue = [&](int k, int b) {
        uint32_t bb = sb + b * 16896;
        int k0 = k * 16;
        moe_cp16(bb + dA,        aH + k0);
        moe_cp16(bb + 6144 + dA, aL + k0);
        moe_cp16(bb + dB, bB + (size_t)k0 * DM);
    };

    const int Ksteps = HID / 16;   // 128
    issue(0, 0); MOE_CP_COMMIT();
    MOE_CP_WAIT0(); __syncthreads();

    for (int k = 0; k < Ksteps; k++) {
        if (k + 1 < Ksteps) issue(k + 1, (k + 1) & 1);
        MOE_CP_COMMIT();

        const char* bb = smem + (k & 1) * 16896;
        const __nv_bfloat16* Ah = (const __nv_bfloat16*)(bb);
        const __nv_bfloat16* Al = (const __nv_bfloat16*)(bb + 6144);
        const __nv_bfloat16* Bh = (const __nv_bfloat16*)(bb + 12288);
        const __nv_bfloat16* Bl = (const __nv_bfloat16*)(bb + 14592);

        wmma::fragment<wmma::matrix_a, 16, 16, 16, __nv_bfloat16, wmma::row_major> afh[2], afl[2];
        wmma::fragment<wmma::matrix_b, 16, 16, 16, __nv_bfloat16, wmma::row_major> bfh[2], bfl[2];
        #pragma unroll
        for (int mi = 0; mi < 2; mi++) {
            wmma::load_matrix_sync(afh[mi], Ah + (warpM + mi * 16) * 24, 24);
            wmma::load_matrix_sync(afl[mi], Al + (warpM + mi * 16) * 24, 24);
        }
        #pragma unroll
        for (int ni = 0; ni < 2; ni++) {
            wmma::load_matrix_sync(bfh[ni], Bh + warpN + ni * 16, 72);
            wmma::load_matrix_sync(bfl[ni], Bl + warpN + ni * 16, 72);
        }
        #pragma unroll
        for (int mi = 0; mi < 2; mi++)
            #pragma unroll
            for (int ni = 0; ni < 2; ni++) {
                wmma::mma_sync(acc[mi][ni], afh[mi], bfh[ni], acc[mi][ni]);
                wmma::mma_sync(acc[mi][ni], afh[mi], bfl[ni], acc[mi][ni]);
                wmma::mma_sync(acc[mi][ni], afl[mi], bfh[ni], acc[mi][ni]);
            }

        MOE_CP_WAIT0(); __syncthreads();
    }

    // epilogue through smem fp32
    float* Sf = (float*)smem;   // [128][68]
    #pragma unroll
    for (int mi = 0; mi < 2; mi++)
        #pragma unroll
        for (int ni = 0; ni < 2; ni++)
            wmma::store_matrix_sync(Sf + (warpM + mi * 16) * 68 + (warpN + ni * 16),
                                    acc[mi][ni], 68, wmma::mem_row_major);
    __syncthreads();

    {
        int row = tid >> 1, cb = (tid & 1) * 32;
        int slot = mBase + row;
        if (slot < r1) {
            const float* s = Sf + row * 68 + cb;
            if (ROUTED) {
                int tok = g_perm_tok[slot];
                float g = g_perm_gate[slot];
                float* dst = out + (size_t)tok * DM + n0 + cb;
                #pragma unroll
                for (int j = 0; j < 32; j++) atomicAdd(dst + j, g * s[j]);
            } else {
                float* dst = out + (size_t)slot * DM + n0 + cb;
                #pragma unroll
                for (int j = 0; j < 8; j++)
                    *(float4*)(dst + 4*j) = *(const float4*)(s + 4*j);
            }
        }
    }
}

// ---------------- launch ----------------
extern "C" void kernel_launch(void* const* d_in, const int* in_sizes, int n_in,
                              void* d_out, int out_size) {
    (void)in_sizes; (void)n_in; (void)out_size;
    const float* x   = (const float*)d_in[0];
    const float* wr  = (const float*)d_in[1];
    const float* w1  = (const float*)d_in[2];
    const float* w3  = (const float*)d_in[3];
    const float* w2  = (const float*)d_in[4];
    const float* sw1 = (const float*)d_in[5];
    const float* sw3 = (const float*)d_in[6];
    const float* sw2 = (const float*)d_in[7];
    float* out = (float*)d_out;

    // device-global destinations for the split pre-pass
    __nv_bfloat16 *p_xh, *p_xl, *p_w1h, *p_w1l, *p_w3h, *p_w3l, *p_w2h, *p_w2l;
    __nv_bfloat16 *p_s1h, *p_s1l, *p_s3h, *p_s3l, *p_s2h, *p_s2l;
    cudaGetSymbolAddress((void**)&p_xh,  g_xh);
    cudaGetSymbolAddress((void**)&p_xl,  g_xl);
    cudaGetSymbolAddress((void**)&p_w1h, g_w1h);
    cudaGetSymbolAddress((void**)&p_w1l, g_w1l);
    cudaGetSymbolAddress((void**)&p_w3h, g_w3h);
    cudaGetSymbolAddress((void**)&p_w3l, g_w3l);
    cudaGetSymbolAddress((void**)&p_w2h, g_w2h);
    cudaGetSymbolAddress((void**)&p_w2l, g_w2l);
    cudaGetSymbolAddress((void**)&p_s1h, g_s1h);
    cudaGetSymbolAddress((void**)&p_s1l, g_s1l);
    cudaGetSymbolAddress((void**)&p_s3h, g_s3h);
    cudaGetSymbolAddress((void**)&p_s3l, g_s3l);
    cudaGetSymbolAddress((void**)&p_s2h, g_s2h);
    cudaGetSymbolAddress((void**)&p_s2l, g_s2l);

    // Routing
    moe_zero_counts<<<1, 32>>>();
    moe_router<<<T_TOK, 256>>>(x, wr);
    moe_scan<<<1, 32>>>();
    moe_scatter<<<(T_TOK + 255) / 256, 256>>>();

    // fp32 -> bf16 hi/lo pre-split (one-time per launch)
    moe_split_kernel<<<(T_TOK * DM) / 1024, 256>>>(x, p_xh, p_xl);
    moe_split_kernel<<<(NE * DM * HID) / 1024, 256>>>(w1, p_w1h, p_w1l);
    moe_split_kernel<<<(NE * DM * HID) / 1024, 256>>>(w3, p_w3h, p_w3l);
    moe_split_kernel<<<(NE * HID * DM) / 1024, 256>>>(w2, p_w2h, p_w2l);
    moe_split_kernel<<<(DM * HID) / 1024, 256>>>(sw1, p_s1h, p_s1l);
    moe_split_kernel<<<(DM * HID) / 1024, 256>>>(sw3, p_s3h, p_s3l);
    moe_split_kernel<<<(HID * DM) / 1024, 256>>>(sw2, p_s2h, p_s2l);

    // Shared expert first (plain stores cover the 0xAA poison in out)
    moe_g1<false><<<dim3(T_TOK / 128, HID / 64, 1), 256>>>(p_s1h, p_s1l, p_s3h, p_s3l, T_TOK);
    moe_g2<false><<<dim3(T_TOK / 128, DM / 64, 1), 256>>>(p_s2h, p_s2l, out, T_TOK);

    // Routed experts (worst-case grid; empty tiles early-exit)
    moe_g1<true><<<dim3(NSLOTS / 128, HID / 64, NE), 256>>>(p_w1h, p_w1l, p_w3h, p_w3l, 0);
    moe_g2<true><<<dim3(NSLOTS / 128, DM / 64, NE), 256>>>(p_w2h, p_w2l, out, 0);
}